// round 16
// baseline (speedup 1.0000x reference)
#include <cuda_runtime.h>

typedef unsigned long long u64;

#define QPB   128    // threads per block
#define TILE  1024   // candidates per phase-1 block (= S / SPLIT)
#define KN    64     // neighbours kept (excluding self)
#define BUF   16     // keys folded into L per merge step (phase 2)
#define UGRP  8      // candidates per group (ILP granularity)
#define SPLIT 4      // candidate-range split (phase-1 grid multiplier)

#define N_MAX 49152
#define CAPR  256              // per-(query,range) scratch capacity
#define CAPQ  (SPLIT * CAPR)

#define KEY_EMPTY 0xFFFFFFFFFFFFFFFFull

// Near-boundary window: d2 bits within +/-512 ulps of 1.0f (radius^2).
#define NEAR_LO   (0x3F800000u - 512u)
#define NEAR_SPAN (1024u)
#define NEAR_HI_F __uint_as_float(0x3F800000u + 512u)

// Static scratch. Transposed: g_keys[slot * N + query] -> phase-2 loads
// (fixed slot, consecutive queries per lane) are fully coalesced.
__device__ u64 g_keys[(size_t)N_MAX * CAPQ];   // ~402 MB
__device__ int g_cnt[N_MAX * SPLIT];

__device__ __forceinline__ void cas_asc(u64 &a, u64 &b) {
    u64 lo = (a < b) ? a : b;
    u64 hi = (a < b) ? b : a;
    a = lo; b = hi;
}

// cuBLAS SIMT SGEMM (K=4): acc=0, ascending FMA chain.
__device__ __forceinline__ float dot4_fma(float4 a, float4 b) {
    float acc = __fmul_rn(a.x, b.x);
    acc = __fmaf_rn(a.y, b.y, acc);
    acc = __fmaf_rn(a.z, b.z, acc);
    acc = __fmaf_rn(a.w, b.w, acc);
    return acc;
}

// XLA row-reduce of x*x: separate rounded squares, sequential adds.
__device__ __forceinline__ float sq4_seq(float4 a) {
    const float p0 = __fmul_rn(a.x, a.x);
    const float p1 = __fmul_rn(a.y, a.y);
    const float p2 = __fmul_rn(a.z, a.z);
    const float p3 = __fmul_rn(a.w, a.w);
    return __fadd_rn(__fadd_rn(__fadd_rn(p0, p1), p2), p3);
}

// Exact (double) d2 for boundary arbitration (rare path only).
__device__ __forceinline__ double d2_true(float4 q, float4 c) {
    const double dx = (double)q.x - c.x, dy = (double)q.y - c.y;
    const double dz = (double)q.z - c.z, dw = (double)q.w - c.w;
    return dx * dx + dy * dy + dz * dz + dw * dw;
}

// ---------------- Phase 1: branchless radius filter -> scratch ----------------
// (R13/R15 verbatim — measured ~180us)
extern "C" __global__ void __launch_bounds__(QPB, 8)
knn_filter_kernel(const float4 *__restrict__ coords, int S, int Ntot) {
    __shared__ float4 sc[TILE];
    __shared__ float  scsq[TILE];

    const int tid = threadIdx.x;
    const int blocksPerSeg = S / QPB;
    const int qgroup = blockIdx.x / SPLIT;
    const int range  = blockIdx.x % SPLIT;
    const int seg = qgroup / blocksPerSeg;
    const int qlocal = (qgroup % blocksPerSeg) * QPB + tid;
    const int segBase = seg * S;
    const int cbase = range * TILE;

    for (int t = tid; t < TILE; t += QPB) {
        float4 c = coords[segBase + cbase + t];
        sc[t] = c;
        scsq[t] = sq4_seq(c);
    }

    const float4 q = coords[segBase + qlocal];
    const float qsq = sq4_seq(q);
    const int query = segBase + qlocal;

    // Running output pointer, stride = Ntot slots (transposed layout).
    u64 *p = g_keys + (size_t)(range * CAPR) * (size_t)Ntot + (size_t)query;
    int cnt = 0;

    __syncthreads();

#pragma unroll 1
    for (int j0 = 0; j0 < TILE; j0 += UGRP) {
#pragma unroll
        for (int u = 0; u < UGRP; ++u) {
            const int j = j0 + u;
            const float4 c = sc[j];
            const float dot = dot4_fma(q, c);
            const float t2 = __fadd_rn(qsq, scsq[j]);
            const float d2 = __fmaf_rn(dot, -2.0f, t2);  // == t2 - rn(2*dot)
            const int gj = cbase + j;
            // branchless predicated push (arbitration deferred to phase 2)
            const bool acc = (d2 <= NEAR_HI_F) && (gj != qlocal) && (cnt < CAPR);
            if (acc) {
                const unsigned db = __float_as_uint(fmaxf(d2, 0.0f));
                *p = (((u64)db) << 32) | (unsigned)gj;
                p += Ntot;
                cnt++;
            }
        }
    }
    g_cnt[range * Ntot + query] = cnt;
}

// ---------------- Phase 2: select top-64 from scratch ----------------

// L is bitonic -> sorted ascending (6 stages x 32 CAS)
__device__ __forceinline__ void merge64(u64 (&L)[KN]) {
#pragma unroll
    for (int d = 32; d >= 1; d >>= 1) {
#pragma unroll
        for (int i = 0; i < KN; ++i) {
            if ((i & d) == 0) cas_asc(L[i], L[i | d]);
        }
    }
}

// Fold BUF keys (EMPTY-padded) into sorted L.
__device__ __forceinline__ void fold16(u64 (&L)[KN], u64 (&B)[BUF]) {
#pragma unroll
    for (int kk = 2; kk <= BUF; kk <<= 1) {
#pragma unroll
        for (int jj = kk >> 1; jj > 0; jj >>= 1) {
#pragma unroll
            for (int i = 0; i < BUF; ++i) {
                int l = i ^ jj;
                if (l > i) {
                    bool up = ((i & kk) == 0);
                    u64 a = B[i], b = B[l];
                    bool sw = up ? (a > b) : (a < b);
                    u64 na = sw ? b : a;
                    u64 nb = sw ? a : b;
                    B[i] = na; B[l] = nb;
                }
            }
        }
    }
#pragma unroll
    for (int i = 0; i < BUF; ++i) {
        u64 b = B[BUF - 1 - i];
        if (b < L[KN - BUF + i]) L[KN - BUF + i] = b;
    }
    merge64(L);
}

extern "C" __global__ void __launch_bounds__(QPB, 2)   // 256-reg ceiling: no spills
knn_select_kernel(const float4 *__restrict__ coords, float *__restrict__ out,
                  int S, int Ntot) {
    const int query = blockIdx.x * QPB + threadIdx.x;
    const int segBase = (query / S) * S;

    const float4 q = coords[query];

    u64 L[KN];
#pragma unroll
    for (int i = 0; i < KN; ++i) L[i] = KEY_EMPTY;

#pragma unroll 1
    for (int r = 0; r < SPLIT; ++r) {
        int n = g_cnt[r * Ntot + query];
        n = (n < CAPR) ? n : CAPR;
        const u64 *rk = g_keys + (size_t)(r * CAPR) * (size_t)Ntot + (size_t)query;
#pragma unroll 1
        for (int base = 0; base < n; base += BUF) {
            u64 B[BUF];
            // 1) pure batched loads — no branches between, MLP = 16
#pragma unroll
            for (int i = 0; i < BUF; ++i) {
                int slot = base + i;
                slot = (slot < n) ? slot : (n - 1);   // clamp addr; SEL later
                B[i] = rk[(size_t)slot * (size_t)Ntot];
            }
            // 2) branchless window-hit mask (no branches, no doubles here)
            unsigned hm = 0;
#pragma unroll
            for (int i = 0; i < BUF; ++i) {
                const unsigned db = (unsigned)(B[i] >> 32);
                hm |= (db - NEAR_LO <= NEAR_SPAN) ? (1u << i) : 0u;
            }
            // 3) rare fix-up: ONE warp-level branch per batch (~11% taken)
            if (__any_sync(0xFFFFFFFFu, hm != 0u)) {
                if (hm) {
#pragma unroll
                    for (int i = 0; i < BUF; ++i) {
                        if (hm & (1u << i)) {
                            u64 k = B[i];
                            const unsigned db = (unsigned)(k >> 32);
                            const int idx = (int)(k & 0xFFFFFFFFu);
                            const float4 c = coords[segBase + idx];
                            if (d2_true(q, c) <= 1.0) {
                                if (db > 0x3F800000u)
                                    k = (((u64)0x3F800000u) << 32) | (unsigned)idx;
                            } else {
                                k = KEY_EMPTY;
                            }
                            B[i] = k;
                        }
                    }
                }
            }
            // 4) validity for the clamped tail
#pragma unroll
            for (int i = 0; i < BUF; ++i) {
                if (base + i >= n) B[i] = KEY_EMPTY;
            }
            // 5) fold into register-resident sorted top-64
            fold16(L, B);
        }
    }

    // ---- Output: [idx (N x 65) as float] then [dist (N x 65)] ----
    const long long row = (long long)query;
    float *__restrict__ oIdx  = out;
    float *__restrict__ oDist = out + (long long)Ntot * 65;

    oIdx[row * 65]  = (float)row;   // self first, global index
    oDist[row * 65] = 0.0f;
#pragma unroll
    for (int k = 0; k < KN; ++k) {
        const u64 key = L[k];
        const unsigned db = (unsigned)(key >> 32);
        const bool valid = (db <= 0x3F800000u);   // d2 <= 1.0; EMPTY fails
        const float fi = valid ? (float)(segBase + (int)(key & 0xFFFFFFFFu)) : -1.0f;
        const float dv = valid ? __uint_as_float(db) : 0.0f;
        oIdx[row * 65 + 1 + k]  = fi;
        oDist[row * 65 + 1 + k] = dv;
    }
}

extern "C" void kernel_launch(void *const *d_in, const int *in_sizes, int n_in,
                              void *d_out, int out_size) {
    const float4 *coords = (const float4 *)d_in[0];
    const int N = in_sizes[0] / 4;       // coordinates: [N, 4] float32
    const int B = in_sizes[1] - 1;       // row_splits: [B+1]
    const int S = N / B;                 // uniform segments (per reference)
    const int grid1 = B * (S / QPB) * SPLIT;
    knn_filter_kernel<<<grid1, QPB>>>(coords, S, N);
    const int grid2 = N / QPB;
    knn_select_kernel<<<grid2, QPB>>>(coords, (float *)d_out, S, N);
}

// round 17
// speedup vs baseline: 1.2908x; 1.2908x over previous
#include <cuda_runtime.h>

typedef unsigned long long u64;

#define QPB   128    // threads per block
#define TILE  1024   // candidates per phase-1 block (= S / SPLIT)
#define KN    64     // neighbours kept (excluding self)
#define BUF   16     // keys folded into L per merge step (phase 2)
#define UGRP  8      // candidates per group (ILP granularity)
#define SPLIT 4      // candidate-range split (phase-1 grid multiplier)

#define N_MAX 49152
#define CAPR  192              // per-(query,range) scratch capacity
#define CAPQ  (SPLIT * CAPR)

#define KEY_EMPTY 0xFFFFFFFFFFFFFFFFull

// Near-boundary window: d2 bits within +/-512 ulps of 1.0f (radius^2).
#define NEAR_LO   (0x3F800000u - 512u)
#define NEAR_SPAN (1024u)
#define NEAR_HI_F __uint_as_float(0x3F800000u + 512u)

// Static scratch, per-query contiguous (R9 layout): each thread's phase-2
// batch of 16 keys lands in one 128B line.
__device__ u64 g_keys[(size_t)N_MAX * CAPQ];
__device__ int g_cnt[N_MAX * SPLIT];

__device__ __forceinline__ void cas_asc(u64 &a, u64 &b) {
    u64 lo = (a < b) ? a : b;
    u64 hi = (a < b) ? b : a;
    a = lo; b = hi;
}

// cuBLAS SIMT SGEMM (K=4): acc=0, ascending FMA chain.
__device__ __forceinline__ float dot4_fma(float4 a, float4 b) {
    float acc = __fmul_rn(a.x, b.x);
    acc = __fmaf_rn(a.y, b.y, acc);
    acc = __fmaf_rn(a.z, b.z, acc);
    acc = __fmaf_rn(a.w, b.w, acc);
    return acc;
}

// XLA row-reduce of x*x: separate rounded squares, sequential adds.
__device__ __forceinline__ float sq4_seq(float4 a) {
    const float p0 = __fmul_rn(a.x, a.x);
    const float p1 = __fmul_rn(a.y, a.y);
    const float p2 = __fmul_rn(a.z, a.z);
    const float p3 = __fmul_rn(a.w, a.w);
    return __fadd_rn(__fadd_rn(__fadd_rn(p0, p1), p2), p3);
}

// Exact (double) d2 for boundary arbitration (phase-1 rare path only).
__device__ __noinline__ double d2_true(float4 q, float4 c) {
    const double dx = (double)q.x - c.x, dy = (double)q.y - c.y;
    const double dz = (double)q.z - c.z, dw = (double)q.w - c.w;
    return dx * dx + dy * dy + dz * dz + dw * dw;
}

// ---------------- Phase 1: branchless radius filter (+rare arbitration) ----------------
extern "C" __global__ void __launch_bounds__(QPB, 8)
knn_filter_kernel(const float4 *__restrict__ coords, int S, int Ntot) {
    __shared__ float4 sc[TILE];
    __shared__ float  scsq[TILE];

    const int tid = threadIdx.x;
    const int blocksPerSeg = S / QPB;
    const int qgroup = blockIdx.x / SPLIT;
    const int range  = blockIdx.x % SPLIT;
    const int seg = qgroup / blocksPerSeg;
    const int qlocal = (qgroup % blocksPerSeg) * QPB + tid;
    const int segBase = seg * S;
    const int cbase = range * TILE;

    for (int t = tid; t < TILE; t += QPB) {
        float4 c = coords[segBase + cbase + t];
        sc[t] = c;
        scsq[t] = sq4_seq(c);
    }

    const float4 q = coords[segBase + qlocal];
    const float qsq = sq4_seq(q);
    const int query = segBase + qlocal;
    u64 *__restrict__ myKeys =
        g_keys + (size_t)query * CAPQ + (size_t)range * CAPR;

    __syncthreads();

    int cnt = 0;
#pragma unroll 1
    for (int j0 = 0; j0 < TILE; j0 += UGRP) {
#pragma unroll
        for (int u = 0; u < UGRP; ++u) {
            const int j = j0 + u;
            const float4 c = sc[j];
            const float dot = dot4_fma(q, c);
            const float t2 = __fadd_rn(qsq, scsq[j]);
            const float d2 = __fmaf_rn(dot, -2.0f, t2);  // == t2 - rn(2*dot)
            const int gj = cbase + j;
            if ((d2 <= NEAR_HI_F) && (gj != qlocal) && (cnt < CAPR)) {  // ~3%
                unsigned db = __float_as_uint(fmaxf(d2, 0.0f));
                bool keep = true;
                if (db - NEAR_LO <= NEAR_SPAN) {      // ~2e-4 of accepts
                    if (d2_true(q, c) <= 1.0) {
                        db = (db > 0x3F800000u) ? 0x3F800000u : db;
                    } else {
                        keep = false;
                    }
                }
                if (keep) {
                    myKeys[cnt] = (((u64)db) << 32) | (unsigned)gj;
                    cnt++;
                }
            }
        }
    }
    g_cnt[query * SPLIT + range] = cnt;
}

// ---------------- Phase 2: select top-64 from scratch (R9 verbatim) ----------------

// L is bitonic -> sorted ascending (6 stages x 32 CAS)
__device__ __forceinline__ void merge64(u64 (&L)[KN]) {
#pragma unroll
    for (int d = 32; d >= 1; d >>= 1) {
#pragma unroll
        for (int i = 0; i < KN; ++i) {
            if ((i & d) == 0) cas_asc(L[i], L[i | d]);
        }
    }
}

// Fold up to BUF keys (B, padded with EMPTY) into sorted L.
__device__ __forceinline__ void fold16(u64 (&L)[KN], u64 (&B)[BUF]) {
#pragma unroll
    for (int kk = 2; kk <= BUF; kk <<= 1) {
#pragma unroll
        for (int jj = kk >> 1; jj > 0; jj >>= 1) {
#pragma unroll
            for (int i = 0; i < BUF; ++i) {
                int l = i ^ jj;
                if (l > i) {
                    bool up = ((i & kk) == 0);
                    u64 a = B[i], b = B[l];
                    bool sw = up ? (a > b) : (a < b);
                    u64 na = sw ? b : a;
                    u64 nb = sw ? a : b;
                    B[i] = na; B[l] = nb;
                }
            }
        }
    }
#pragma unroll
    for (int i = 0; i < BUF; ++i) {
        u64 b = B[BUF - 1 - i];
        if (b < L[KN - BUF + i]) L[KN - BUF + i] = b;
    }
    merge64(L);
}

extern "C" __global__ void __launch_bounds__(QPB, 3)
knn_select_kernel(float *__restrict__ out, int S, int Ntot) {
    const int query = blockIdx.x * QPB + threadIdx.x;
    const int segBase = (query / S) * S;

    u64 L[KN];
#pragma unroll
    for (int i = 0; i < KN; ++i) L[i] = KEY_EMPTY;

    const u64 *__restrict__ qKeys = g_keys + (size_t)query * CAPQ;
#pragma unroll 1
    for (int r = 0; r < SPLIT; ++r) {
        const int n = g_cnt[query * SPLIT + r];
        const u64 *__restrict__ rk = qKeys + r * CAPR;
#pragma unroll 1
        for (int base = 0; base < n; base += BUF) {
            u64 B[BUF];
#pragma unroll
            for (int i = 0; i < BUF; ++i) {
                B[i] = (base + i < n) ? rk[base + i] : KEY_EMPTY;
            }
            fold16(L, B);
        }
    }

    // ---- Output: [idx (N x 65) as float] then [dist (N x 65)] ----
    const long long row = (long long)query;
    float *__restrict__ oIdx  = out;
    float *__restrict__ oDist = out + (long long)Ntot * 65;

    oIdx[row * 65]  = (float)row;   // self first, global index
    oDist[row * 65] = 0.0f;
#pragma unroll
    for (int k = 0; k < KN; ++k) {
        const u64 key = L[k];
        const unsigned db = (unsigned)(key >> 32);
        const bool valid = (db <= 0x3F800000u);   // d2 <= 1.0; EMPTY fails
        const float fi = valid ? (float)(segBase + (int)(key & 0xFFFFFFFFu)) : -1.0f;
        const float dv = valid ? __uint_as_float(db) : 0.0f;
        oIdx[row * 65 + 1 + k]  = fi;
        oDist[row * 65 + 1 + k] = dv;
    }
}

extern "C" void kernel_launch(void *const *d_in, const int *in_sizes, int n_in,
                              void *d_out, int out_size) {
    const float4 *coords = (const float4 *)d_in[0];
    const int N = in_sizes[0] / 4;       // coordinates: [N, 4] float32
    const int B = in_sizes[1] - 1;       // row_splits: [B+1]
    const int S = N / B;                 // uniform segments (per reference)
    const int grid1 = B * (S / QPB) * SPLIT;
    knn_filter_kernel<<<grid1, QPB>>>(coords, S, N);
    const int grid2 = N / QPB;
    knn_select_kernel<<<grid2, QPB>>>((float *)d_out, S, N);
}